// round 5
// baseline (speedup 1.0000x reference)
#include <cuda_runtime.h>
#include <cuda_bf16.h>

// Discriminator_73598559584743
// out[b, n]     = cos(s[b,n,:], h_rl[b,n,:])
// out[b, N + n] = cos(s[b,n,:], h_fk[b,n,:])
// F.normalize semantics: x / max(||x||_2, 1e-12)
// Shapes: B=8, N=8192, D=512 (fp32). Output [B, 2N] fp32.
//
// HBM/LTS-bound streaming reduction, running at ~98% of the measured
// B300 LTS ceiling (~6.9 TB/s). Persistent grid-stride: one wave of
// 12 CTAs/SM; each warp loops rows. Next-iteration loads are register-
// independent of the current iteration's shfl epilogue, letting ptxas
// overlap them. Body = proven best shape: 12 front-batched LDG.128.

#define D_DIM 512
#define N_DIM 8192
#define EPS 1e-12f

__global__ void __launch_bounds__(128) disc_kernel(
    const float4* __restrict__ s,
    const float4* __restrict__ rl,
    const float4* __restrict__ fk,
    float* __restrict__ out,
    int n_rows)
{
    const int lane        = threadIdx.x & 31;
    const int warp_gid    = blockIdx.x * 4 + (threadIdx.x >> 5);
    const int warps_total = gridDim.x * 4;

    for (int row = warp_gid; row < n_rows; row += warps_total) {
        const size_t base = (size_t)row * (D_DIM / 4) + lane;  // 128 float4/row
        const float4* sp = s  + base;
        const float4* rp = rl + base;
        const float4* fp = fk + base;

        // Front-batch all 12 loads: max independent LDG.128 in flight.
        float4 a0 = sp[ 0], a1 = sp[32], a2 = sp[64], a3 = sp[96];
        float4 b0 = rp[ 0], b1 = rp[32], b2 = rp[64], b3 = rp[96];
        float4 c0 = fp[ 0], c1 = fp[32], c2 = fp[64], c3 = fp[96];

        float ss = 0.f, rr = 0.f, ff = 0.f, srl = 0.f, sfk = 0.f;

#define ACC(a, b, c)                                              \
        ss  += a.x*a.x + a.y*a.y + a.z*a.z + a.w*a.w;             \
        rr  += b.x*b.x + b.y*b.y + b.z*b.z + b.w*b.w;             \
        ff  += c.x*c.x + c.y*c.y + c.z*c.z + c.w*c.w;             \
        srl += a.x*b.x + a.y*b.y + a.z*b.z + a.w*b.w;             \
        sfk += a.x*c.x + a.y*c.y + a.z*c.z + a.w*c.w;

        ACC(a0, b0, c0)
        ACC(a1, b1, c1)
        ACC(a2, b2, c2)
        ACC(a3, b3, c3)
#undef ACC

        // Warp tree reduction of the 5 partials.
#pragma unroll
        for (int off = 16; off > 0; off >>= 1) {
            ss  += __shfl_xor_sync(0xFFFFFFFFu, ss,  off);
            rr  += __shfl_xor_sync(0xFFFFFFFFu, rr,  off);
            ff  += __shfl_xor_sync(0xFFFFFFFFu, ff,  off);
            srl += __shfl_xor_sync(0xFFFFFFFFu, srl, off);
            sfk += __shfl_xor_sync(0xFFFFFFFFu, sfk, off);
        }

        if (lane == 0) {
            const float ns  = fmaxf(sqrtf(ss), EPS);
            const float nrl = fmaxf(sqrtf(rr), EPS);
            const float nfk = fmaxf(sqrtf(ff), EPS);
            const int b = row >> 13;          // row / 8192
            const int n = row & (N_DIM - 1);  // row % 8192
            float* ob = out + (size_t)b * (2 * N_DIM);
            ob[n]         = srl / (ns * nrl);
            ob[N_DIM + n] = sfk / (ns * nfk);
        }
    }
}

extern "C" void kernel_launch(void* const* d_in, const int* in_sizes, int n_in,
                              void* d_out, int out_size)
{
    const float4* s  = (const float4*)d_in[0];
    const float4* rl = (const float4*)d_in[1];
    const float4* fk = (const float4*)d_in[2];
    float* out = (float*)d_out;

    const int n_rows = in_sizes[0] / D_DIM;   // 65536

    // Persistent single wave: 12 CTAs/SM on 152 SMs (GB300).
    // Grid-stride loop is robust to actual SM count / occupancy.
    const int blocks = 152 * 12;              // 1824 CTAs, 4 warps each

    disc_kernel<<<blocks, 128>>>(s, rl, fk, out, n_rows);
}

// round 6
// speedup vs baseline: 1.1317x; 1.1317x over previous
#include <cuda_runtime.h>
#include <cuda_bf16.h>

// Discriminator_73598559584743
// out[b, n]     = cos(s[b,n,:], h_rl[b,n,:])
// out[b, N + n] = cos(s[b,n,:], h_fk[b,n,:])
// F.normalize semantics: x / max(||x||_2, 1e-12)
// Shapes: B=8, N=8192, D=512 (fp32). Output [B, 2N] fp32.
//
// HBM/LTS-bound streaming reduction (~98% of measured LTS ceiling).
// Two consecutive rows per warp, straight-line: row0's ACC FMAs overlap
// row1's load flight; one shared shfl/sqrt/store epilogue amortizes
// per-warp dead time. 12 front-batched LDG.128 per row (proven shape).

#define D_DIM 512
#define N_DIM 8192
#define EPS 1e-12f

__global__ void __launch_bounds__(128) disc_kernel(
    const float4* __restrict__ s,
    const float4* __restrict__ rl,
    const float4* __restrict__ fk,
    float* __restrict__ out,
    int n_pairs)   // pairs of rows; row = 2*pair
{
    const int lane = threadIdx.x & 31;
    const int pair = blockIdx.x * 4 + (threadIdx.x >> 5);
    if (pair >= n_pairs) return;

    const int row0 = pair * 2;
    const size_t base = (size_t)row0 * (D_DIM / 4) + lane;  // 128 float4/row
    const float4* sp = s  + base;
    const float4* rp = rl + base;
    const float4* fp = fk + base;

#define ACC(a, b, c, i)                                               \
    ss##i  += a.x*a.x + a.y*a.y + a.z*a.z + a.w*a.w;                  \
    rr##i  += b.x*b.x + b.y*b.y + b.z*b.z + b.w*b.w;                  \
    ff##i  += c.x*c.x + c.y*c.y + c.z*c.z + c.w*c.w;                  \
    srl##i += a.x*b.x + a.y*b.y + a.z*b.z + a.w*b.w;                  \
    sfk##i += a.x*c.x + a.y*c.y + a.z*c.z + a.w*c.w;

    // ---- Row 0: front-batch 12 loads ----
    float4 a0 = sp[ 0], a1 = sp[32], a2 = sp[64], a3 = sp[96];
    float4 b0 = rp[ 0], b1 = rp[32], b2 = rp[64], b3 = rp[96];
    float4 c0 = fp[ 0], c1 = fp[32], c2 = fp[64], c3 = fp[96];

    float ss0 = 0.f, rr0 = 0.f, ff0 = 0.f, srl0 = 0.f, sfk0 = 0.f;
    ACC(a0, b0, c0, 0)
    ACC(a1, b1, c1, 0)
    ACC(a2, b2, c2, 0)
    ACC(a3, b3, c3, 0)

    // ---- Row 1: front-batch 12 loads (reuses a*/b*/c* registers) ----
    a0 = sp[128 +  0]; a1 = sp[128 + 32]; a2 = sp[128 + 64]; a3 = sp[128 + 96];
    b0 = rp[128 +  0]; b1 = rp[128 + 32]; b2 = rp[128 + 64]; b3 = rp[128 + 96];
    c0 = fp[128 +  0]; c1 = fp[128 + 32]; c2 = fp[128 + 64]; c3 = fp[128 + 96];

    float ss1 = 0.f, rr1 = 0.f, ff1 = 0.f, srl1 = 0.f, sfk1 = 0.f;
    ACC(a0, b0, c0, 1)
    ACC(a1, b1, c1, 1)
    ACC(a2, b2, c2, 1)
    ACC(a3, b3, c3, 1)
#undef ACC

    // ---- Shared epilogue: warp tree reduction of all 10 partials ----
#pragma unroll
    for (int off = 16; off > 0; off >>= 1) {
        ss0  += __shfl_xor_sync(0xFFFFFFFFu, ss0,  off);
        rr0  += __shfl_xor_sync(0xFFFFFFFFu, rr0,  off);
        ff0  += __shfl_xor_sync(0xFFFFFFFFu, ff0,  off);
        srl0 += __shfl_xor_sync(0xFFFFFFFFu, srl0, off);
        sfk0 += __shfl_xor_sync(0xFFFFFFFFu, sfk0, off);
        ss1  += __shfl_xor_sync(0xFFFFFFFFu, ss1,  off);
        rr1  += __shfl_xor_sync(0xFFFFFFFFu, rr1,  off);
        ff1  += __shfl_xor_sync(0xFFFFFFFFu, ff1,  off);
        srl1 += __shfl_xor_sync(0xFFFFFFFFu, srl1, off);
        sfk1 += __shfl_xor_sync(0xFFFFFFFFu, sfk1, off);
    }

    if (lane == 0) {
        const int b = row0 >> 13;            // row0 / 8192
        const int n = row0 & (N_DIM - 1);    // row0 % 8192 (row1 = n+1, same b)
        float* ob = out + (size_t)b * (2 * N_DIM);

        float ns  = fmaxf(sqrtf(ss0), EPS);
        float nrl = fmaxf(sqrtf(rr0), EPS);
        float nfk = fmaxf(sqrtf(ff0), EPS);
        ob[n]             = srl0 / (ns * nrl);
        ob[N_DIM + n]     = sfk0 / (ns * nfk);

        ns  = fmaxf(sqrtf(ss1), EPS);
        nrl = fmaxf(sqrtf(rr1), EPS);
        nfk = fmaxf(sqrtf(ff1), EPS);
        ob[n + 1]         = srl1 / (ns * nrl);
        ob[N_DIM + n + 1] = sfk1 / (ns * nfk);
    }
}

extern "C" void kernel_launch(void* const* d_in, const int* in_sizes, int n_in,
                              void* d_out, int out_size)
{
    const float4* s  = (const float4*)d_in[0];
    const float4* rl = (const float4*)d_in[1];
    const float4* fk = (const float4*)d_in[2];
    float* out = (float*)d_out;

    const int n_rows  = in_sizes[0] / D_DIM;  // 65536
    const int n_pairs = n_rows / 2;           // 32768 (N=8192 even, rows pair within batch)
    const int blocks  = (n_pairs + 3) / 4;    // one warp per pair, 4 warps/CTA

    disc_kernel<<<blocks, 128>>>(s, rl, fk, out, n_pairs);
}

// round 7
// speedup vs baseline: 1.1400x; 1.0073x over previous
#include <cuda_runtime.h>
#include <cuda_bf16.h>

// Discriminator_73598559584743
// out[b, n]     = cos(s[b,n,:], h_rl[b,n,:])
// out[b, N + n] = cos(s[b,n,:], h_fk[b,n,:])
// F.normalize semantics: x / max(||x||_2, 1e-12)
// Shapes: B=8, N=8192, D=512 (fp32). Output [B, 2N] fp32.
//
// HBM/LTS-bound streaming reduction at ~98% of the measured B300 LTS
// chip ceiling (~6.9 TB/s, path-independent). Proven shape: one warp
// per row, 12 front-batched LDG.128, natural registers, flat grid of
// 4-warp CTAs. This round: interleaved (s,rl,fk) load issue order to
// smooth LTS queue burstiness across the three address streams.

#define D_DIM 512
#define N_DIM 8192
#define EPS 1e-12f

__global__ void __launch_bounds__(128) disc_kernel(
    const float4* __restrict__ s,
    const float4* __restrict__ rl,
    const float4* __restrict__ fk,
    float* __restrict__ out,
    int n_rows)
{
    const int row  = blockIdx.x * 4 + (threadIdx.x >> 5);
    const int lane = threadIdx.x & 31;
    if (row >= n_rows) return;

    const size_t base = (size_t)row * (D_DIM / 4) + lane;  // 128 float4 per row
    const float4* sp = s  + base;
    const float4* rp = rl + base;
    const float4* fp = fk + base;

    // Front-batch all 12 loads, interleaved across the three streams.
    float4 a0 = sp[ 0], b0 = rp[ 0], c0 = fp[ 0];
    float4 a1 = sp[32], b1 = rp[32], c1 = fp[32];
    float4 a2 = sp[64], b2 = rp[64], c2 = fp[64];
    float4 a3 = sp[96], b3 = rp[96], c3 = fp[96];

    float ss = 0.f, rr = 0.f, ff = 0.f, srl = 0.f, sfk = 0.f;

#define ACC(a, b, c)                                              \
    ss  += a.x*a.x + a.y*a.y + a.z*a.z + a.w*a.w;                 \
    rr  += b.x*b.x + b.y*b.y + b.z*b.z + b.w*b.w;                 \
    ff  += c.x*c.x + c.y*c.y + c.z*c.z + c.w*c.w;                 \
    srl += a.x*b.x + a.y*b.y + a.z*b.z + a.w*b.w;                 \
    sfk += a.x*c.x + a.y*c.y + a.z*c.z + a.w*c.w;

    ACC(a0, b0, c0)
    ACC(a1, b1, c1)
    ACC(a2, b2, c2)
    ACC(a3, b3, c3)
#undef ACC

    // Warp tree reduction of the 5 partials.
#pragma unroll
    for (int off = 16; off > 0; off >>= 1) {
        ss  += __shfl_xor_sync(0xFFFFFFFFu, ss,  off);
        rr  += __shfl_xor_sync(0xFFFFFFFFu, rr,  off);
        ff  += __shfl_xor_sync(0xFFFFFFFFu, ff,  off);
        srl += __shfl_xor_sync(0xFFFFFFFFu, srl, off);
        sfk += __shfl_xor_sync(0xFFFFFFFFu, sfk, off);
    }

    if (lane == 0) {
        const float ns  = fmaxf(sqrtf(ss), EPS);
        const float nrl = fmaxf(sqrtf(rr), EPS);
        const float nfk = fmaxf(sqrtf(ff), EPS);
        const int b = row >> 13;            // row / 8192
        const int n = row & (N_DIM - 1);    // row % 8192
        float* ob = out + (size_t)b * (2 * N_DIM);
        ob[n]         = srl / (ns * nrl);
        ob[N_DIM + n] = sfk / (ns * nfk);
    }
}

extern "C" void kernel_launch(void* const* d_in, const int* in_sizes, int n_in,
                              void* d_out, int out_size)
{
    const float4* s  = (const float4*)d_in[0];
    const float4* rl = (const float4*)d_in[1];
    const float4* fk = (const float4*)d_in[2];
    float* out = (float*)d_out;

    const int n_rows = in_sizes[0] / D_DIM;   // 65536
    const int blocks = (n_rows + 3) / 4;      // one warp per row, 4 warps/CTA

    disc_kernel<<<blocks, 128>>>(s, rl, fk, out, n_rows);
}

// round 8
// speedup vs baseline: 1.1513x; 1.0100x over previous
#include <cuda_runtime.h>
#include <cuda_bf16.h>

// Discriminator_73598559584743
// out[b, n]     = cos(s[b,n,:], h_rl[b,n,:])
// out[b, N + n] = cos(s[b,n,:], h_fk[b,n,:])
// F.normalize semantics: x / max(||x||_2, 1e-12)
// Shapes: B=8, N=8192, D=512 (fp32). Output [B, 2N] fp32.
//
// HBM/LTS-bound streaming reduction at ~99% of the measured B300 LTS
// chip ceiling (~6.9 TB/s, path-independent). Proven shape: one warp
// per row, 12 front-batched interleaved LDG.128, natural registers,
// flat grid of 4-warp CTAs. This round: __ldcs (evict-first) on the
// read-once streams — the one remaining untested orthogonal knob.

#define D_DIM 512
#define N_DIM 8192
#define EPS 1e-12f

__global__ void __launch_bounds__(128) disc_kernel(
    const float4* __restrict__ s,
    const float4* __restrict__ rl,
    const float4* __restrict__ fk,
    float* __restrict__ out,
    int n_rows)
{
    const int row  = blockIdx.x * 4 + (threadIdx.x >> 5);
    const int lane = threadIdx.x & 31;
    if (row >= n_rows) return;

    const size_t base = (size_t)row * (D_DIM / 4) + lane;  // 128 float4 per row
    const float4* sp = s  + base;
    const float4* rp = rl + base;
    const float4* fp = fk + base;

    // Front-batch all 12 loads, interleaved across the three streams.
    // __ldcs: data is touched exactly once — evict-first in L2.
    float4 a0 = __ldcs(sp +  0), b0 = __ldcs(rp +  0), c0 = __ldcs(fp +  0);
    float4 a1 = __ldcs(sp + 32), b1 = __ldcs(rp + 32), c1 = __ldcs(fp + 32);
    float4 a2 = __ldcs(sp + 64), b2 = __ldcs(rp + 64), c2 = __ldcs(fp + 64);
    float4 a3 = __ldcs(sp + 96), b3 = __ldcs(rp + 96), c3 = __ldcs(fp + 96);

    float ss = 0.f, rr = 0.f, ff = 0.f, srl = 0.f, sfk = 0.f;

#define ACC(a, b, c)                                              \
    ss  += a.x*a.x + a.y*a.y + a.z*a.z + a.w*a.w;                 \
    rr  += b.x*b.x + b.y*b.y + b.z*b.z + b.w*b.w;                 \
    ff  += c.x*c.x + c.y*c.y + c.z*c.z + c.w*c.w;                 \
    srl += a.x*b.x + a.y*b.y + a.z*b.z + a.w*b.w;                 \
    sfk += a.x*c.x + a.y*c.y + a.z*c.z + a.w*c.w;

    ACC(a0, b0, c0)
    ACC(a1, b1, c1)
    ACC(a2, b2, c2)
    ACC(a3, b3, c3)
#undef ACC

    // Warp tree reduction of the 5 partials.
#pragma unroll
    for (int off = 16; off > 0; off >>= 1) {
        ss  += __shfl_xor_sync(0xFFFFFFFFu, ss,  off);
        rr  += __shfl_xor_sync(0xFFFFFFFFu, rr,  off);
        ff  += __shfl_xor_sync(0xFFFFFFFFu, ff,  off);
        srl += __shfl_xor_sync(0xFFFFFFFFu, srl, off);
        sfk += __shfl_xor_sync(0xFFFFFFFFu, sfk, off);
    }

    if (lane == 0) {
        const float ns  = fmaxf(sqrtf(ss), EPS);
        const float nrl = fmaxf(sqrtf(rr), EPS);
        const float nfk = fmaxf(sqrtf(ff), EPS);
        const int b = row >> 13;            // row / 8192
        const int n = row & (N_DIM - 1);    // row % 8192
        float* ob = out + (size_t)b * (2 * N_DIM);
        ob[n]         = srl / (ns * nrl);
        ob[N_DIM + n] = sfk / (ns * nfk);
    }
}

extern "C" void kernel_launch(void* const* d_in, const int* in_sizes, int n_in,
                              void* d_out, int out_size)
{
    const float4* s  = (const float4*)d_in[0];
    const float4* rl = (const float4*)d_in[1];
    const float4* fk = (const float4*)d_in[2];
    float* out = (float*)d_out;

    const int n_rows = in_sizes[0] / D_DIM;   // 65536
    const int blocks = (n_rows + 3) / 4;      // one warp per row, 4 warps/CTA

    disc_kernel<<<blocks, 128>>>(s, rl, fk, out, n_rows);
}